// round 1
// baseline (speedup 1.0000x reference)
#include <cuda_runtime.h>
#include <math.h>

// Problem constants (from reference)
#define BS 2
#define CH 100
#define T 100
#define D 50
#define KNN 3
#define RES_INNER 12
#define RES_CTX 16
#define RES_TOT (RES_INNER + RES_CTX)   // 28
#define OUT_TOTAL (BS * CH * RES_TOT * D * T)  // 28,000,000

// scratch: ctx[b][t][k]  (b,t as (B,C) for the second align1d; L = KNN = 3)
__device__ float g_ctx[BS * T * KNN];

// -------- Kernel 1: kNN (cubed-norm pseudo-distance) + ctx = mean_c x[b,c,nbr] --------
// one block per (b,t); 128 threads; thread s<100 computes pd[s]
__global__ void knn_ctx_kernel(const float* __restrict__ x) {
    const int bt = blockIdx.x;
    const int b  = bt / T;
    const int t  = bt % T;
    const int s  = threadIdx.x;

    __shared__ float sh_dot[T];
    __shared__ float sh_xx[T];
    __shared__ float sh_pd[T];
    __shared__ int   sh_idx[KNN];

    const float* xb = x + (size_t)b * CH * T;

    if (s < T) {
        float dot = 0.0f, x3 = 0.0f;
        #pragma unroll 4
        for (int c = 0; c < CH; ++c) {
            float xs = xb[c * T + s];
            float xt = xb[c * T + t];
            dot += xt * xs;
            x3  += xs * xs * xs;
        }
        sh_dot[s] = dot;
        sh_xx[s]  = x3;
    }
    __syncthreads();

    if (s < T) {
        // pd = -xx_t + 2*dot - xx_s   (ref: -xx - inner - xx^T, inner = -2 dot)
        sh_pd[s] = 2.0f * sh_dot[s] - sh_xx[t] - sh_xx[s];
    }
    __syncthreads();

    // thread 0: top-3, ties -> lowest index (strictly-greater replacement, ascending scan)
    if (s == 0) {
        int taken0 = -1, taken1 = -1;
        #pragma unroll
        for (int k = 0; k < KNN; ++k) {
            float best = -INFINITY;
            int bi = 0;
            for (int i = 0; i < T; ++i) {
                if (i == taken0 || i == taken1) continue;
                float v = sh_pd[i];
                if (v > best) { best = v; bi = i; }
            }
            sh_idx[k] = bi;
            if (k == 0) taken0 = bi; else if (k == 1) taken1 = bi;
        }
    }
    __syncthreads();

    // threads 0..2: ctx[b,t,k] = mean over channels of x[b, c, idx_k]
    if (s < KNN) {
        int nb = sh_idx[s];
        float sum = 0.0f;
        for (int c = 0; c < CH; ++c) sum += xb[c * T + nb];
        g_ctx[(b * T + t) * KNN + s] = sum / (float)CH;
    }
}

// -------- Kernel 2: fused align1d(inner) + align1d(context) + layout --------
// out[b, c*28+r, d, t]; linear index i -> t fastest (coalesced stores)
__global__ void graph_align_main(const float* __restrict__ x,
                                 float* __restrict__ out) {
    int i = blockIdx.x * blockDim.x + threadIdx.x;
    if (i >= OUT_TOTAL) return;

    int t = i % T;
    int j = i / T;
    int d = j % D;  j /= D;
    int r = j % RES_TOT; j /= RES_TOT;
    int c = j % CH;
    int b = j / CH;

    // analytic anchor (bit-exact vs make_anchors: values are exact halves)
    bool va = (t + d) < T;
    float cl    = (float)(d + 1);
    float start = va ? ((float)t - cl * 0.5f) : 0.0f;
    float end   = va ? ((float)(t + d) + cl * 0.5f) : 0.0f;

    float result;
    if (r < RES_INNER) {
        float binw  = __fdiv_rn(end - start, (float)RES_INNER);
        float coord = __fadd_rn(start, __fmul_rn((float)r + 0.5f, binw));
        bool valid  = (coord >= -1.0f) && (coord <= (float)T);
        float lo    = floorf(coord);
        float frac  = coord - lo;
        int loi = (int)lo;
        loi = loi < 0 ? 0 : (loi > T - 1 ? T - 1 : loi);
        int hii = loi + 1 > T - 1 ? T - 1 : loi + 1;
        const float* xr = x + ((size_t)b * CH + c) * T;
        float v = xr[loi] * (1.0f - frac) + xr[hii] * frac;
        result = valid ? v : 0.0f;
    } else {
        int rr = r - RES_INNER;
        float binw  = __fdiv_rn(end - start, (float)RES_CTX);
        float coord = __fadd_rn(start, __fmul_rn((float)rr + 0.5f, binw));
        bool valid  = (coord >= -1.0f) && (coord <= (float)KNN);
        float lo    = floorf(coord);
        float frac  = coord - lo;
        int loi = (int)lo;
        loi = loi < 0 ? 0 : (loi > KNN - 1 ? KNN - 1 : loi);
        int hii = loi + 1 > KNN - 1 ? KNN - 1 : loi + 1;
        const float* cr = g_ctx + (b * CH + c) * KNN;  // ctx "channel" = t-index c
        float v = cr[loi] * (1.0f - frac) + cr[hii] * frac;
        result = valid ? v : 0.0f;
    }
    out[i] = result;
}

extern "C" void kernel_launch(void* const* d_in, const int* in_sizes, int n_in,
                              void* d_out, int out_size) {
    const float* x = (const float*)d_in[0];
    // d_in[1] = anchors (recomputed analytically), d_in[2] = index (unused by reference)
    float* out = (float*)d_out;

    knn_ctx_kernel<<<BS * T, 128>>>(x);

    const int threads = 256;
    const int blocks  = (OUT_TOTAL + threads - 1) / threads;  // 109375
    graph_align_main<<<blocks, threads>>>(x, out);
}

// round 2
// speedup vs baseline: 2.6986x; 2.6986x over previous
#include <cuda_runtime.h>
#include <math.h>

#define BS 2
#define CH 100
#define T 100
#define D 50
#define KNN 3
#define RES_INNER 12
#define RES_CTX 16
#define RES_TOT (RES_INNER + RES_CTX)          // 28
#define DT (D * T)                              // 5000
#define OUT_C_STRIDE (RES_TOT * DT)             // 140000
#define NT_TILES 5                              // 5 tiles of 1024 dt-positions (256 thr x 4)

__device__ float g_ctx[BS * T * KNN];

// -------- Kernel 1: kNN (cubed-norm pseudo-distance) + ctx means --------
// one block per (b,t); 128 threads
__global__ void knn_ctx_kernel(const float* __restrict__ x) {
    const int bt = blockIdx.x;
    const int b  = bt / T;
    const int t  = bt % T;
    const int tid = threadIdx.x;

    __shared__ float sh_dot[T];
    __shared__ float sh_xx[T];
    __shared__ float sh_pd[T];
    __shared__ int   sh_idx[KNN];

    const float* xb = x + (size_t)b * CH * T;

    if (tid < T) {
        float dot = 0.0f, x3 = 0.0f;
        #pragma unroll 4
        for (int c = 0; c < CH; ++c) {
            float xs = xb[c * T + tid];
            float xt = xb[c * T + t];
            dot += xt * xs;
            x3  += xs * xs * xs;
        }
        sh_dot[tid] = dot;
        sh_xx[tid]  = x3;
    }
    __syncthreads();

    if (tid < T) {
        // pd = (2*dot - xx_t) - xx_s   (same rounding order as ref elementwise ops)
        sh_pd[tid] = 2.0f * sh_dot[tid] - sh_xx[t] - sh_xx[tid];
    }
    __syncthreads();

    // top-3 via warp-0 argmax, ties -> lowest index (matches lax.top_k)
    if (tid < 32) {
        #pragma unroll
        for (int k = 0; k < KNN; ++k) {
            float bv = -INFINITY; int bi = T;
            for (int i = tid; i < T; i += 32) {
                float v = sh_pd[i];
                if (v > bv) { bv = v; bi = i; }   // ascending i + strict > => lowest index
            }
            #pragma unroll
            for (int off = 16; off > 0; off >>= 1) {
                float ov = __shfl_down_sync(0xffffffffu, bv, off);
                int   oi = __shfl_down_sync(0xffffffffu, bi, off);
                if (ov > bv || (ov == bv && oi < bi)) { bv = ov; bi = oi; }
            }
            bi = __shfl_sync(0xffffffffu, bi, 0);
            if (tid == 0) { sh_idx[k] = bi; sh_pd[bi] = -INFINITY; }
            __syncwarp();
        }
    }
    __syncthreads();

    // ctx[b,t,k] = mean over channels of x[b,c,idx_k]; warp k handles neighbor k
    int w = tid >> 5, lane = tid & 31;
    if (w < KNN) {
        int nb = sh_idx[w];
        float sum = 0.0f;
        for (int c = lane; c < CH; c += 32) sum += xb[c * T + nb];
        #pragma unroll
        for (int off = 16; off > 0; off >>= 1)
            sum += __shfl_down_sync(0xffffffffu, sum, off);
        if (lane == 0) g_ctx[(b * T + t) * KNN + w] = sum / (float)CH;
    }
}

// -------- Kernel 2: fused align1d (inner + context) with hoisted coefficients --------
// grid: b * RES_TOT * NT_TILES; block 256 threads; thread owns 4 consecutive dt
__global__ __launch_bounds__(256)
void graph_align_main(const float* __restrict__ x, float* __restrict__ out) {
    int blk  = blockIdx.x;
    int tile = blk % NT_TILES; blk /= NT_TILES;
    int r    = blk % RES_TOT;
    int b    = blk / RES_TOT;

    int dt0 = tile * 1024 + threadIdx.x * 4;
    if (dt0 >= DT) return;

    const bool inner = (r < RES_INNER);
    const int  L     = inner ? T : KNN;
    const int  res   = inner ? RES_INNER : RES_CTX;
    const int  rr    = inner ? r : r - RES_INNER;

    int   lo[4], hi[4];
    float wlo[4], whi[4];

    #pragma unroll
    for (int j = 0; j < 4; ++j) {
        int dt = dt0 + j;
        int d  = dt / T;
        int t  = dt - d * T;
        bool va     = (t + d) < T;
        float cl    = (float)(d + 1);
        float start = va ? ((float)t - cl * 0.5f) : 0.0f;
        float end   = va ? ((float)(t + d) + cl * 0.5f) : 0.0f;
        float binw  = __fdiv_rn(end - start, (float)res);
        float coord = __fadd_rn(start, __fmul_rn((float)rr + 0.5f, binw));
        bool valid  = (coord >= -1.0f) && (coord <= (float)L);
        float lof   = floorf(coord);
        float frac  = coord - lof;
        int loi = (int)lof;
        loi = loi < 0 ? 0 : (loi > L - 1 ? L - 1 : loi);
        int hii = loi + 1 > L - 1 ? L - 1 : loi + 1;
        lo[j] = loi; hi[j] = hii;
        wlo[j] = valid ? (1.0f - frac) : 0.0f;
        whi[j] = valid ? frac : 0.0f;
    }

    int outbase = ((b * CH) * RES_TOT + r) * DT + dt0;   // c = 0

    if (inner) {
        const float* src = x + (size_t)b * CH * T;
        #pragma unroll 4
        for (int c = 0; c < CH; ++c) {
            float4 v;
            v.x = wlo[0] * src[lo[0]] + whi[0] * src[hi[0]];
            v.y = wlo[1] * src[lo[1]] + whi[1] * src[hi[1]];
            v.z = wlo[2] * src[lo[2]] + whi[2] * src[hi[2]];
            v.w = wlo[3] * src[lo[3]] + whi[3] * src[hi[3]];
            *reinterpret_cast<float4*>(out + outbase) = v;
            src += T;
            outbase += OUT_C_STRIDE;
        }
    } else {
        const float* src = g_ctx + b * CH * KNN;   // ctx "channel" dim = t' (CH==T)
        #pragma unroll 4
        for (int c = 0; c < CH; ++c) {
            float4 v;
            v.x = wlo[0] * src[lo[0]] + whi[0] * src[hi[0]];
            v.y = wlo[1] * src[lo[1]] + whi[1] * src[hi[1]];
            v.z = wlo[2] * src[lo[2]] + whi[2] * src[hi[2]];
            v.w = wlo[3] * src[lo[3]] + whi[3] * src[hi[3]];
            *reinterpret_cast<float4*>(out + outbase) = v;
            src += KNN;
            outbase += OUT_C_STRIDE;
        }
    }
}

extern "C" void kernel_launch(void* const* d_in, const int* in_sizes, int n_in,
                              void* d_out, int out_size) {
    const float* x = (const float*)d_in[0];
    float* out = (float*)d_out;

    knn_ctx_kernel<<<BS * T, 128>>>(x);

    const int grid = BS * RES_TOT * NT_TILES;   // 280
    graph_align_main<<<grid, 256>>>(x, out);
}

// round 3
// speedup vs baseline: 3.4033x; 1.2611x over previous
#include <cuda_runtime.h>
#include <math.h>

#define BS 2
#define CH 100
#define T 100
#define D 50
#define KNN 3
#define RES_INNER 12
#define RES_CTX 16
#define RES_TOT (RES_INNER + RES_CTX)          // 28
#define DT (D * T)                              // 5000
#define OUT_C_STRIDE (RES_TOT * DT)             // 140000
#define NT_TILES 5                              // 5 tiles of 1024 dt-positions (256 thr x 4)
#define CSPLIT 4                                // channel split across blocks
#define C_PER_BLK (CH / CSPLIT)                 // 25

__device__ float g_ctx[BS * T * KNN];

// -------- Kernel 1: kNN (cubed-norm pseudo-distance) + ctx means --------
// one block per (b,t); 128 threads; colsum fused into phase 1
__global__ void knn_ctx_kernel(const float* __restrict__ x) {
    const int bt = blockIdx.x;
    const int b  = bt / T;
    const int t  = bt % T;
    const int tid = threadIdx.x;

    __shared__ float sh_pd[T];
    __shared__ float sh_colsum[T];
    __shared__ float sh_xxt;

    const float* xb = x + (size_t)b * CH * T;

    if (tid < T) {
        float dot0 = 0.0f, dot1 = 0.0f;
        float x30 = 0.0f, x31 = 0.0f;
        float cs0 = 0.0f, cs1 = 0.0f;
        #pragma unroll 4
        for (int c = 0; c < CH; c += 2) {
            float xs0 = xb[c * T + tid];
            float xt0 = xb[c * T + t];
            float xs1 = xb[(c + 1) * T + tid];
            float xt1 = xb[(c + 1) * T + t];
            dot0 += xt0 * xs0;  dot1 += xt1 * xs1;
            x30  += xs0 * xs0 * xs0;  x31 += xs1 * xs1 * xs1;
            cs0  += xs0;  cs1 += xs1;
        }
        float dot = dot0 + dot1;
        float x3  = x30 + x31;
        sh_colsum[tid] = cs0 + cs1;
        if (tid == t) sh_xxt = x3;
        // pd finished after we know xx_t:
        sh_pd[tid] = 2.0f * dot - x3;   // still missing -xx_t
    }
    __syncthreads();

    if (tid < T) sh_pd[tid] = sh_pd[tid] - sh_xxt;
    __syncthreads();

    // top-3 via warp-0 argmax, ties -> lowest index (matches lax.top_k)
    if (tid < 32) {
        #pragma unroll
        for (int k = 0; k < KNN; ++k) {
            float bv = -INFINITY; int bi = T;
            #pragma unroll
            for (int i = tid; i < T; i += 32) {
                float v = sh_pd[i];
                if (v > bv) { bv = v; bi = i; }   // ascending i + strict > => lowest index
            }
            #pragma unroll
            for (int off = 16; off > 0; off >>= 1) {
                float ov = __shfl_down_sync(0xffffffffu, bv, off);
                int   oi = __shfl_down_sync(0xffffffffu, bi, off);
                if (ov > bv || (ov == bv && oi < bi)) { bv = ov; bi = oi; }
            }
            bi = __shfl_sync(0xffffffffu, bi, 0);
            if (tid == 0) {
                g_ctx[(b * T + t) * KNN + k] = sh_colsum[bi] / (float)CH;
                sh_pd[bi] = -INFINITY;
            }
            __syncwarp();
        }
    }
}

// -------- Kernel 2: fused align1d (inner + context), coeff hoisted, c-split --------
// grid: b * RES_TOT * NT_TILES * CSPLIT; 256 threads; thread owns 4 consecutive dt
__global__ __launch_bounds__(256)
void graph_align_main(const float* __restrict__ x, float* __restrict__ out) {
    int blk  = blockIdx.x;
    int cblk = blk % CSPLIT; blk /= CSPLIT;
    int tile = blk % NT_TILES; blk /= NT_TILES;
    int r    = blk % RES_TOT;
    int b    = blk / RES_TOT;

    int dt0 = tile * 1024 + threadIdx.x * 4;
    if (dt0 >= DT) return;

    const bool inner = (r < RES_INNER);
    const int  L     = inner ? T : KNN;
    const int  res   = inner ? RES_INNER : RES_CTX;
    const int  rr    = inner ? r : r - RES_INNER;

    int   lo[4], hi[4];
    float wlo[4], whi[4];

    #pragma unroll
    for (int j = 0; j < 4; ++j) {
        int dt = dt0 + j;
        int d  = dt / T;
        int t  = dt - d * T;
        bool va     = (t + d) < T;
        float cl    = (float)(d + 1);
        float start = va ? ((float)t - cl * 0.5f) : 0.0f;
        float end   = va ? ((float)(t + d) + cl * 0.5f) : 0.0f;
        float binw  = __fdiv_rn(end - start, (float)res);
        float coord = __fadd_rn(start, __fmul_rn((float)rr + 0.5f, binw));
        bool valid  = (coord >= -1.0f) && (coord <= (float)L);
        float lof   = floorf(coord);
        float frac  = coord - lof;
        int loi = (int)lof;
        loi = loi < 0 ? 0 : (loi > L - 1 ? L - 1 : loi);
        int hii = loi + 1 > L - 1 ? L - 1 : loi + 1;
        lo[j] = loi; hi[j] = hii;
        wlo[j] = valid ? (1.0f - frac) : 0.0f;
        whi[j] = valid ? frac : 0.0f;
    }

    const int c0 = cblk * C_PER_BLK;
    int outbase = (((b * CH + c0)) * RES_TOT + r) * DT + dt0;

    if (inner) {
        const float* src = x + ((size_t)b * CH + c0) * T;
        #pragma unroll 5
        for (int c = 0; c < C_PER_BLK; ++c) {
            float4 v;
            v.x = wlo[0] * src[lo[0]] + whi[0] * src[hi[0]];
            v.y = wlo[1] * src[lo[1]] + whi[1] * src[hi[1]];
            v.z = wlo[2] * src[lo[2]] + whi[2] * src[hi[2]];
            v.w = wlo[3] * src[lo[3]] + whi[3] * src[hi[3]];
            *reinterpret_cast<float4*>(out + outbase) = v;
            src += T;
            outbase += OUT_C_STRIDE;
        }
    } else {
        const float* src = g_ctx + (b * CH + c0) * KNN;   // ctx "channel" dim = t' (CH==T)
        #pragma unroll 5
        for (int c = 0; c < C_PER_BLK; ++c) {
            float4 v;
            v.x = wlo[0] * src[lo[0]] + whi[0] * src[hi[0]];
            v.y = wlo[1] * src[lo[1]] + whi[1] * src[hi[1]];
            v.z = wlo[2] * src[lo[2]] + whi[2] * src[hi[2]];
            v.w = wlo[3] * src[lo[3]] + whi[3] * src[hi[3]];
            *reinterpret_cast<float4*>(out + outbase) = v;
            src += KNN;
            outbase += OUT_C_STRIDE;
        }
    }
}

extern "C" void kernel_launch(void* const* d_in, const int* in_sizes, int n_in,
                              void* d_out, int out_size) {
    const float* x = (const float*)d_in[0];
    float* out = (float*)d_out;

    knn_ctx_kernel<<<BS * T, 128>>>(x);

    const int grid = BS * RES_TOT * NT_TILES * CSPLIT;   // 1120
    graph_align_main<<<grid, 256>>>(x, out);
}

// round 4
// speedup vs baseline: 4.2153x; 1.2386x over previous
#include <cuda_runtime.h>
#include <math.h>

#define BS 2
#define CH 100
#define T 100
#define D 50
#define KNN 3
#define RES_INNER 12
#define RES_CTX 16
#define RES_TOT (RES_INNER + RES_CTX)          // 28
#define DT (D * T)                              // 5000
#define OUT_C_STRIDE (RES_TOT * DT)             // 140000
#define NT_TILES 5                              // ceil(5000/1024)
#define CSPLIT 4
#define C_PER_BLK (CH / CSPLIT)                 // 25

__device__ float g_ctx[BS * T * KNN];

// -------- Kernel 1: kNN + ctx means; 512 thr, 4-way channel split --------
__global__ __launch_bounds__(512)
void knn_ctx_kernel(const float* __restrict__ x) {
    const int bt = blockIdx.x;
    const int b  = bt / T;
    const int t  = bt % T;
    const int tid = threadIdx.x;
    const int q   = tid >> 7;          // quarter 0..3 (25 channels each)
    const int s   = tid & 127;         // position 0..127 (active <100)

    __shared__ float sh_dot[4][T];
    __shared__ float sh_x3[4][T];
    __shared__ float sh_cs[4][T];
    __shared__ float sh_pd[T];
    __shared__ float sh_colsum[T];
    __shared__ float sh_xxt;

    const float* xb = x + (size_t)b * CH * T;

    if (s < T) {
        const int c0 = q * 25;
        float dot = 0.0f, x3 = 0.0f, cs = 0.0f;
        #pragma unroll 5
        for (int c = c0; c < c0 + 25; ++c) {
            float xs = xb[c * T + s];
            float xt = xb[c * T + t];
            dot = fmaf(xt, xs, dot);
            x3  = fmaf(xs * xs, xs, x3);
            cs += xs;
        }
        sh_dot[q][s] = dot;
        sh_x3[q][s]  = x3;
        sh_cs[q][s]  = cs;
    }
    __syncthreads();

    if (tid < T) {
        float dot = (sh_dot[0][tid] + sh_dot[1][tid]) + (sh_dot[2][tid] + sh_dot[3][tid]);
        float x3  = (sh_x3[0][tid]  + sh_x3[1][tid])  + (sh_x3[2][tid]  + sh_x3[3][tid]);
        sh_colsum[tid] = (sh_cs[0][tid] + sh_cs[1][tid]) + (sh_cs[2][tid] + sh_cs[3][tid]);
        if (tid == t) sh_xxt = x3;
        sh_pd[tid] = 2.0f * dot - x3;       // -xx_t applied after sync
    }
    __syncthreads();
    if (tid < T) sh_pd[tid] = sh_pd[tid] - sh_xxt;
    __syncthreads();

    // top-3 (warp 0), ties -> lowest index (matches lax.top_k)
    if (tid < 32) {
        #pragma unroll
        for (int k = 0; k < KNN; ++k) {
            float bv = -INFINITY; int bi = T;
            #pragma unroll
            for (int i = tid; i < T; i += 32) {
                float v = sh_pd[i];
                if (v > bv) { bv = v; bi = i; }
            }
            #pragma unroll
            for (int off = 16; off > 0; off >>= 1) {
                float ov = __shfl_down_sync(0xffffffffu, bv, off);
                int   oi = __shfl_down_sync(0xffffffffu, bi, off);
                if (ov > bv || (ov == bv && oi < bi)) { bv = ov; bi = oi; }
            }
            bi = __shfl_sync(0xffffffffu, bi, 0);
            if (tid == 0) {
                g_ctx[(b * T + t) * KNN + k] = sh_colsum[bi] / (float)CH;
                sh_pd[bi] = -INFINITY;
            }
            __syncwarp();
        }
    }
}

// -------- Kernel 2: fused align1d, block-strided element mapping --------
// element j of thread tid: dt = tile*1024 + j*256 + tid  (lanes consecutive!)
__global__ __launch_bounds__(256)
void graph_align_main(const float* __restrict__ x, float* __restrict__ out) {
    int blk  = blockIdx.x;
    int cblk = blk % CSPLIT;  blk /= CSPLIT;
    int tile = blk % NT_TILES; blk /= NT_TILES;
    int r    = blk % RES_TOT;
    int b    = blk / RES_TOT;
    int tid  = threadIdx.x;

    const bool inner = (r < RES_INNER);
    const int  L     = inner ? T : KNN;
    const int  res   = inner ? RES_INNER : RES_CTX;
    const int  rr    = inner ? r : r - RES_INNER;

    int   dtv[4], lo[4], hi[4];
    float wlo[4], whi[4];
    bool  ok[4];

    #pragma unroll
    for (int j = 0; j < 4; ++j) {
        int dt = tile * 1024 + j * 256 + tid;
        dtv[j] = dt;
        ok[j]  = (dt < DT);
        int dd = dt < DT ? dt : 0;
        int d  = dd / T;
        int t  = dd - d * T;
        bool va     = (t + d) < T;
        float cl    = (float)(d + 1);
        float start = va ? ((float)t - cl * 0.5f) : 0.0f;
        float end   = va ? ((float)(t + d) + cl * 0.5f) : 0.0f;
        float binw  = __fdiv_rn(end - start, (float)res);
        float coord = __fadd_rn(start, __fmul_rn((float)rr + 0.5f, binw));
        bool valid  = (coord >= -1.0f) && (coord <= (float)L);
        float lof   = floorf(coord);
        float frac  = coord - lof;
        int loi = (int)lof;
        loi = loi < 0 ? 0 : (loi > L - 1 ? L - 1 : loi);
        int hii = loi + 1 > L - 1 ? L - 1 : loi + 1;
        lo[j] = loi; hi[j] = hii;
        wlo[j] = valid ? (1.0f - frac) : 0.0f;
        whi[j] = valid ? frac : 0.0f;
    }

    const int c0 = cblk * C_PER_BLK;
    int outbase = ((b * CH + c0) * RES_TOT + r) * DT;

    const float* src = inner ? (x + ((size_t)b * CH + c0) * T)
                             : (g_ctx + (b * CH + c0) * KNN);
    const int srcstride = inner ? T : KNN;

    #pragma unroll 5
    for (int c = 0; c < C_PER_BLK; ++c) {
        #pragma unroll
        for (int j = 0; j < 4; ++j) {
            if (ok[j]) {
                float v = fmaf(whi[j], __ldg(src + hi[j]), wlo[j] * __ldg(src + lo[j]));
                out[outbase + dtv[j]] = v;
            }
        }
        src += srcstride;
        outbase += OUT_C_STRIDE;
    }
}

extern "C" void kernel_launch(void* const* d_in, const int* in_sizes, int n_in,
                              void* d_out, int out_size) {
    const float* x = (const float*)d_in[0];
    float* out = (float*)d_out;

    knn_ctx_kernel<<<BS * T, 512>>>(x);

    const int grid = BS * RES_TOT * NT_TILES * CSPLIT;   // 1120
    graph_align_main<<<grid, 256>>>(x, out);
}

// round 5
// speedup vs baseline: 4.6875x; 1.1120x over previous
#include <cuda_runtime.h>
#include <math.h>

#define BS 2
#define CH 100
#define T 100
#define D 50
#define KNN 3
#define RES_INNER 12
#define RES_CTX 16
#define RES_TOT 28
#define DT 5000
#define OUT_C_STRIDE 140000
#define NT_TILES 5
#define CSPLIT 10
#define C_PER_BLK 10

#define KNN_GRID  (BS * T)                                   // 200
#define INNER_GRID (BS * RES_INNER * NT_TILES * CSPLIT)      // 1200
#define K1_GRID   (KNN_GRID + INNER_GRID)                    // 1400
#define CTX_GRID  (BS * RES_CTX * NT_TILES * CSPLIT)         // 1600

__device__ float g_ctx[BS * T * KNN];

// ---------------- kNN body: one block per (b,t); 256 thr, 2-way channel split ----------------
__device__ void knn_body(const float* __restrict__ x, int bt) {
    const int b = bt / T, t = bt % T;
    const int tid = threadIdx.x;
    const int q = tid >> 7;        // half 0/1 (50 channels each)
    const int s = tid & 127;

    __shared__ float sh_dot[2][T], sh_x3[2][T], sh_cs[2][T];
    __shared__ float sh_pd[T], sh_colsum[T], sh_xxt;

    const float* xb = x + (size_t)b * CH * T;

    if (s < T) {
        const int c0 = q * 50;
        float dot = 0.f, x3 = 0.f, cs = 0.f;
        #pragma unroll 5
        for (int c = c0; c < c0 + 50; ++c) {
            float xs = xb[c * T + s];
            float xt = xb[c * T + t];
            dot = fmaf(xt, xs, dot);
            x3  = fmaf(xs * xs, xs, x3);
            cs += xs;
        }
        sh_dot[q][s] = dot; sh_x3[q][s] = x3; sh_cs[q][s] = cs;
    }
    __syncthreads();

    if (tid < T) {
        float dot = sh_dot[0][tid] + sh_dot[1][tid];
        float x3  = sh_x3[0][tid]  + sh_x3[1][tid];
        sh_colsum[tid] = sh_cs[0][tid] + sh_cs[1][tid];
        if (tid == t) sh_xxt = x3;
        sh_pd[tid] = 2.0f * dot - x3;        // -xx_t applied after sync
    }
    __syncthreads();
    if (tid < T) sh_pd[tid] -= sh_xxt;
    __syncthreads();

    // top-3 (warp 0), ties -> lowest index (matches lax.top_k)
    if (tid < 32) {
        #pragma unroll
        for (int k = 0; k < KNN; ++k) {
            float bv = -INFINITY; int bi = T;
            #pragma unroll
            for (int i = tid; i < T; i += 32) {
                float v = sh_pd[i];
                if (v > bv) { bv = v; bi = i; }
            }
            #pragma unroll
            for (int off = 16; off > 0; off >>= 1) {
                float ov = __shfl_down_sync(0xffffffffu, bv, off);
                int   oi = __shfl_down_sync(0xffffffffu, bi, off);
                if (ov > bv || (ov == bv && oi < bi)) { bv = ov; bi = oi; }
            }
            bi = __shfl_sync(0xffffffffu, bi, 0);
            if (tid == 0) {
                g_ctx[(b * T + t) * KNN + k] = sh_colsum[bi] / (float)CH;
                sh_pd[bi] = -INFINITY;
            }
            __syncwarp();
        }
    }
}

// ---------------- K1: kNN blocks + inner align (r < 12), block-strided ----------------
__global__ __launch_bounds__(256)
void k1_inner_knn(const float* __restrict__ x, float* __restrict__ out) {
    if (blockIdx.x < KNN_GRID) { knn_body(x, blockIdx.x); return; }

    int blk  = blockIdx.x - KNN_GRID;
    int cblk = blk % CSPLIT;  blk /= CSPLIT;
    int tile = blk % NT_TILES; blk /= NT_TILES;
    int r    = blk % RES_INNER;
    int b    = blk / RES_INNER;
    int tid  = threadIdx.x;

    int   dtv[4], lo[4], hi[4];
    float wlo[4], whi[4];
    bool  ok[4];

    #pragma unroll
    for (int j = 0; j < 4; ++j) {
        int dt = tile * 1024 + j * 256 + tid;      // lanes consecutive -> coalesced loads
        dtv[j] = dt;
        ok[j]  = (dt < DT);
        int dd = ok[j] ? dt : 0;
        int d  = dd / T;
        int t  = dd - d * T;
        bool va     = (t + d) < T;
        float cl    = (float)(d + 1);
        float start = va ? ((float)t - cl * 0.5f) : 0.0f;
        float end   = va ? ((float)(t + d) + cl * 0.5f) : 0.0f;
        float binw  = __fdiv_rn(end - start, (float)RES_INNER);
        float coord = __fadd_rn(start, __fmul_rn((float)r + 0.5f, binw));
        bool valid  = (coord >= -1.0f) && (coord <= (float)T);
        float lof   = floorf(coord);
        float frac  = coord - lof;
        int loi = (int)lof;
        loi = loi < 0 ? 0 : (loi > T - 1 ? T - 1 : loi);
        int hii = loi + 1 > T - 1 ? T - 1 : loi + 1;
        lo[j] = loi; hi[j] = hii;
        wlo[j] = valid ? (1.0f - frac) : 0.0f;
        whi[j] = valid ? frac : 0.0f;
    }

    const int c0 = cblk * C_PER_BLK;
    const float* src = x + ((size_t)b * CH + c0) * T;
    int outbase = ((b * CH + c0) * RES_TOT + r) * DT;

    #pragma unroll
    for (int c = 0; c < C_PER_BLK; ++c) {
        #pragma unroll
        for (int j = 0; j < 4; ++j) {
            if (ok[j]) {
                float v = fmaf(whi[j], __ldg(src + hi[j]), wlo[j] * __ldg(src + lo[j]));
                out[outbase + dtv[j]] = v;
            }
        }
        src += T;
        outbase += OUT_C_STRIDE;
    }
}

// ---------------- K2: ctx align (r >= 12): 3-coeff precompute, zero hot-loop loads, STG.128 ----------------
__global__ __launch_bounds__(256)
void k2_ctx(float* __restrict__ out) {
    int blk  = blockIdx.x;
    int cblk = blk % CSPLIT;  blk /= CSPLIT;
    int tile = blk % NT_TILES; blk /= NT_TILES;
    int rr   = blk % RES_CTX;
    int b    = blk / RES_CTX;

    int dt0 = tile * 1024 + threadIdx.x * 4;     // thread owns 4 consecutive dt
    if (dt0 >= DT) return;                        // DT%4==0 -> no partial vectors

    float a0[4], a1[4], a2[4];

    #pragma unroll
    for (int j = 0; j < 4; ++j) {
        int dt = dt0 + j;
        int d  = dt / T;
        int t  = dt - d * T;
        bool va     = (t + d) < T;
        float cl    = (float)(d + 1);
        float start = va ? ((float)t - cl * 0.5f) : 0.0f;
        float end   = va ? ((float)(t + d) + cl * 0.5f) : 0.0f;
        float binw  = __fdiv_rn(end - start, (float)RES_CTX);
        float coord = __fadd_rn(start, __fmul_rn((float)rr + 0.5f, binw));
        bool valid  = (coord >= -1.0f) && (coord <= (float)KNN);
        float lof   = floorf(coord);
        float frac  = coord - lof;
        int loi = (int)lof;
        loi = loi < 0 ? 0 : (loi > KNN - 1 ? KNN - 1 : loi);
        int hii = loi + 1 > KNN - 1 ? KNN - 1 : loi + 1;
        float wlo = valid ? (1.0f - frac) : 0.0f;
        float whi = valid ? frac : 0.0f;
        float c0a = 0.f, c1a = 0.f, c2a = 0.f;
        if (loi == 0) c0a += wlo; else if (loi == 1) c1a += wlo; else c2a += wlo;
        if (hii == 0) c0a += whi; else if (hii == 1) c1a += whi; else c2a += whi;
        a0[j] = c0a; a1[j] = c1a; a2[j] = c2a;
    }

    const int c0 = cblk * C_PER_BLK;
    const float* cr = g_ctx + (b * CH + c0) * KNN;
    int outbase = ((b * CH + c0) * RES_TOT + (RES_INNER + rr)) * DT + dt0;

    #pragma unroll
    for (int c = 0; c < C_PER_BLK; ++c) {
        float g0 = cr[0], g1 = cr[1], g2 = cr[2];
        float4 v;
        v.x = fmaf(a2[0], g2, fmaf(a1[0], g1, a0[0] * g0));
        v.y = fmaf(a2[1], g2, fmaf(a1[1], g1, a0[1] * g0));
        v.z = fmaf(a2[2], g2, fmaf(a1[2], g1, a0[2] * g0));
        v.w = fmaf(a2[3], g2, fmaf(a1[3], g1, a0[3] * g0));
        *reinterpret_cast<float4*>(out + outbase) = v;
        cr += KNN;
        outbase += OUT_C_STRIDE;
    }
}

extern "C" void kernel_launch(void* const* d_in, const int* in_sizes, int n_in,
                              void* d_out, int out_size) {
    const float* x = (const float*)d_in[0];
    float* out = (float*)d_out;

    k1_inner_knn<<<K1_GRID, 256>>>(x, out);   // knn overlapped with inner align
    k2_ctx<<<CTX_GRID, 256>>>(out);           // depends on g_ctx (stream order)
}